// round 16
// baseline (speedup 1.0000x reference)
#include <cuda_runtime.h>
#include <cuda_bf16.h>
#include <cuda_fp16.h>
#include <math.h>
#include <stdint.h>

#define TT   16
#define NN   2048
#define EE   16384
#define ELN  8192
#define TNV  (TT*NN)   /* 32768 */
#define TEV  (TT*EE)   /* 262144 */
#define HID  128
#define DIN  64

// ---------------- fp32 scratch ----------------
__device__ float g_deg[TNV];
__device__ float g_dinv[TNV];
__device__ int   g_cntA[TNV];
__device__ int   g_offA[TNV+1];
__device__ int   g_curA[TNV];
__device__ int   g_cntB[NN];
__device__ int   g_offB[NN+1];
__device__ int   g_curB[NN];
__device__ int   g_srcA[TEV];
__device__ float g_normA[TEV];
__device__ int   g_srcB[TEV];

__device__ __align__(16) float g_xw1[TNV*HID];
__device__ __align__(16) float g_xw2[TNV*HID];

__device__ __align__(16) float g_xwg1[(size_t)TNV*512];
__device__ float g_as1[TNV*4];
__device__ float g_ad1[TNV*4];
__device__ __align__(16) float g_xwg2[TNV*64];
__device__ float g_as2[TNV];
__device__ float g_ad2[TNV];
__device__ __align__(16) float g_z2 [TNV*64];

#define BUF_EXT   (-1)
#define BUF_XW1   0
#define BUF_XW2   2
#define BUF_XWG1  5
#define BUF_XWG2  7

template<int ID>
__device__ __forceinline__ float* gbuf() {
    if (ID == BUF_XW1)  return g_xw1;
    if (ID == BUF_XW2)  return g_xw2;
    if (ID == BUF_XWG1) return g_xwg1;
    if (ID == BUF_XWG2) return g_xwg2;
    return nullptr;
}

// ---------------- fp16 operand buffers (raw 2-byte storage) ----------------
__device__ __align__(16) __half h_xh [TNV*DIN];
__device__ __align__(16) __half h_xl [TNV*DIN];
__device__ __align__(16) __half h_h1h[TNV*HID];
__device__ __align__(16) __half h_h1l[TNV*HID];
__device__ __align__(16) __half h_h2h[TNV*HID];
__device__ __align__(16) __half h_h2l[TNV*HID];
__device__ __align__(16) __half h_z1h[(size_t)TNV*512];
__device__ __align__(16) __half h_z1l[(size_t)TNV*512];
__device__ __align__(16) __half h_c1w[HID*DIN];
__device__ __align__(16) __half h_c2w[HID*HID];
__device__ __align__(16) __half h_g1w[512*DIN];
__device__ __align__(16) __half h_g2w[64*512];
__device__ __align__(16) __half h_wf [NN*HID];

#define HF_XH  0
#define HF_XL  1
#define HF_H1H 2
#define HF_H1L 3
#define HF_H2H 4
#define HF_H2L 5
#define HF_Z1H 6
#define HF_Z1L 7
#define HF_C1W 8
#define HF_C2W 9
#define HF_G1W 10
#define HF_G2W 11
#define HF_WF  12

template<int ID>
__device__ __forceinline__ __half* ghf() {
    if (ID == HF_XH)  return h_xh;
    if (ID == HF_XL)  return h_xl;
    if (ID == HF_H1H) return h_h1h;
    if (ID == HF_H1L) return h_h1l;
    if (ID == HF_H2H) return h_h2h;
    if (ID == HF_H2L) return h_h2l;
    if (ID == HF_Z1H) return h_z1h;
    if (ID == HF_Z1L) return h_z1l;
    if (ID == HF_C1W) return h_c1w;
    if (ID == HF_C2W) return h_c2w;
    if (ID == HF_G1W) return h_g1w;
    if (ID == HF_G2W) return h_g2w;
    if (ID == HF_WF)  return h_wf;
    return nullptr;
}

// ---------------- helpers ----------------
__device__ __forceinline__ uint32_t packhf2(float e0, float e1) {
    uint32_t a = (uint32_t)__half_as_ushort(__float2half_rn(e0));
    uint32_t b = (uint32_t)__half_as_ushort(__float2half_rn(e1));
    return (b << 16) | a;
}
__device__ __forceinline__ float hf_hi_f(float x) {
    return __half2float(__float2half_rn(x));
}

// ---------------- setup kernels ----------------
__global__ void k_init() {
    int i = blockIdx.x*blockDim.x + threadIdx.x;
    if (i < TNV) { g_deg[i]=0.f; g_cntA[i]=0; g_curA[i]=0; }
    if (i < NN)  { g_cntB[i]=0; g_curB[i]=0; }
}

__global__ void k_hist(const int* __restrict__ ei, const float* __restrict__ ea) {
    int idx = blockIdx.x*blockDim.x + threadIdx.x;
    if (idx >= TEV) return;
    int t = idx >> 14, e = idx & (EE-1);
    int dst = ei[(t*2+1)*EE + e] & (NN-1);
    float w = ea[idx];
    atomicAdd(&g_deg[t*NN+dst], w);
    atomicAdd(&g_cntA[t*NN+dst], 1);
    atomicAdd(&g_cntB[dst], 1);
}

__device__ void scan_impl(const int* cnt, int* off, int n) {
    __shared__ int part[1024];
    int tid = threadIdx.x;
    int per = n / 1024;
    int base = tid * per;
    int s = 0;
    for (int i = 0; i < per; i++) s += cnt[base+i];
    part[tid] = s; __syncthreads();
    for (int d = 1; d < 1024; d <<= 1) {
        int v = (tid >= d) ? part[tid-d] : 0;
        __syncthreads();
        part[tid] += v;
        __syncthreads();
    }
    int run = (tid == 0) ? 0 : part[tid-1];
    for (int i = 0; i < per; i++) { off[base+i] = run; run += cnt[base+i]; }
    if (tid == 1023) off[n] = run;
}
__global__ void k_scanA() { scan_impl(g_cntA, g_offA, TNV); }
__global__ void k_scanB() { scan_impl(g_cntB, g_offB, NN); }

__global__ void k_dinv() {
    int i = blockIdx.x*blockDim.x + threadIdx.x;
    if (i < TNV) g_dinv[i] = 1.0f / sqrtf(g_deg[i] + 1.0f);
}

__global__ void k_fill(const int* __restrict__ ei, const float* __restrict__ ea) {
    int idx = blockIdx.x*blockDim.x + threadIdx.x;
    if (idx >= TEV) return;
    int t = idx >> 14, e = idx & (EE-1);
    int src = ei[(t*2  )*EE + e] & (NN-1);
    int dst = ei[(t*2+1)*EE + e] & (NN-1);
    float w = ea[idx];
    float nm = g_dinv[t*NN+src] * w * g_dinv[t*NN+dst];
    int bA = t*NN + dst;
    int p = atomicAdd(&g_curA[bA], 1);
    int slot = g_offA[bA] + p;
    g_srcA[slot] = t*NN + src;
    g_normA[slot] = nm;
    int q = atomicAdd(&g_curB[dst], 1);
    g_srcB[g_offB[dst] + q] = src;
}

// weff = W[:, :128] + W[:, 128:], emitted directly as single fp16
__global__ void k_weff_f16(const float* __restrict__ fcw) {
    int i = blockIdx.x*blockDim.x + threadIdx.x;   // u32 pair index
    if (i >= NN*HID/2) return;
    int e = 2*i;
    int r = e >> 7, c = e & 127;
    float v0 = fcw[r*256 + c]     + fcw[r*256 + 128 + c];
    float v1 = fcw[r*256 + c + 1] + fcw[r*256 + 128 + c + 1];
    ((uint32_t*)h_wf)[i] = packhf2(v0, v1);
}

// fp32 -> fp16 hi/lo (for x)
template<int DH, int DL>
__global__ void k_cvt_hl(const float* __restrict__ src, int n4) {
    uint32_t* dh = (uint32_t*)ghf<DH>();
    uint32_t* dl = (uint32_t*)ghf<DL>();
    int i = blockIdx.x*blockDim.x + threadIdx.x;
    if (i >= n4) return;
    float4 v = ((const float4*)src)[i];
    dh[2*i]   = packhf2(v.x, v.y);
    dh[2*i+1] = packhf2(v.z, v.w);
    dl[2*i]   = packhf2(v.x - hf_hi_f(v.x), v.y - hf_hi_f(v.y));
    dl[2*i+1] = packhf2(v.z - hf_hi_f(v.z), v.w - hf_hi_f(v.w));
}

// fp32 -> single fp16 (weights)
template<int D_>
__global__ void k_cvt_w(const float* __restrict__ src, int n4) {
    uint32_t* d = (uint32_t*)ghf<D_>();
    int i = blockIdx.x*blockDim.x + threadIdx.x;
    if (i >= n4) return;
    float4 v = ((const float4*)src)[i];
    d[2*i]   = packhf2(v.x, v.y);
    d[2*i+1] = packhf2(v.z, v.w);
}

// ======= fp16 2-term GEMM: C = (Ah+Al)*B^T, 3-stage cp.async ring, XOR swizzle =======
__device__ __forceinline__ void mma16h(float* c, const uint32_t* a, uint32_t b0, uint32_t b1) {
    asm volatile("mma.sync.aligned.m16n8k16.row.col.f32.f16.f16.f32 "
                 "{%0,%1,%2,%3}, {%4,%5,%6,%7}, {%8,%9}, {%0,%1,%2,%3};"
                 : "+f"(c[0]), "+f"(c[1]), "+f"(c[2]), "+f"(c[3])
                 : "r"(a[0]), "r"(a[1]), "r"(a[2]), "r"(a[3]), "r"(b0), "r"(b1));
}
__device__ __forceinline__ void ldsm4(uint32_t* r, uint32_t a) {
    asm volatile("ldmatrix.sync.aligned.m8n8.x4.shared.b16 {%0,%1,%2,%3}, [%4];"
                 : "=r"(r[0]), "=r"(r[1]), "=r"(r[2]), "=r"(r[3]) : "r"(a));
}
#define CP16(dst, src) asm volatile("cp.async.cg.shared.global [%0], [%1], 16;" :: "r"(dst), "l"(src) : "memory")
#define CP_COMMIT()    asm volatile("cp.async.commit_group;" ::: "memory")
#define CP_WAIT2()     asm volatile("cp.async.wait_group 2;" ::: "memory")
#define CP_WAIT1()     asm volatile("cp.async.wait_group 1;" ::: "memory")
#define CP_WAIT0()     asm volatile("cp.async.wait_group 0;" ::: "memory")

__device__ __forceinline__ uint32_t swz(int r, int cbyte) {
    return (uint32_t)(r*64 + ((((cbyte >> 4) ^ ((r >> 1) & 3)) & 3) << 4));
}

template<int BN, int AH_, int AL_, int B_, int CID>
__global__ __launch_bounds__(256, 2)
void mma_pipe_a2b1(const float* __restrict__ bias, float* __restrict__ Cext,
                   int M, int Nc, int K) {
    extern __shared__ char smem[];
    constexpr int TILE_A = 128*64;
    constexpr int TILE_B = BN*64;
    constexpr int ST  = 2*TILE_A + TILE_B;
    constexpr int AHO = 0, ALO = TILE_A, BO = 2*TILE_A;
    constexpr int WN = BN/2, NT = WN/8, NP = NT/2;

    const __half* Ah = ghf<AH_>();
    const __half* Al = ghf<AL_>();
    const __half* Bp = ghf<B_>();
    float* C = (CID < 0) ? Cext : gbuf<CID>();

    const int tid = threadIdx.x;
    const int wid = tid >> 5, lane = tid & 31;
    const int wr = wid & 3, wc = wid >> 2;
    const int m0 = wr * 32, n0 = wc * WN;
    const int bm = blockIdx.y * 128, bn = blockIdx.x * BN;
    const int g = lane >> 3, lr8 = lane & 7;
    const int ra = m0 + (g & 1)*8 + lr8;  const int ca = (g >> 1) * 16;
    const int rb = n0 + (g >> 1)*8 + lr8; const int cb = (g & 1) * 16;
    uint32_t sbase = (uint32_t)__cvta_generic_to_shared(smem);

    float acc[2][NT][4];
    #pragma unroll
    for (int i = 0; i < 2; i++)
        #pragma unroll
        for (int j = 0; j < NT; j++)
            #pragma unroll
            for (int q = 0; q < 4; q++) acc[i][j][q] = 0.f;

    auto load_stage = [&](int kb, int s) {
        const int kk = kb * 32;
        uint32_t sb = sbase + s*ST;
        #pragma unroll
        for (int i = tid; i < 128*4; i += 256) {
            int r = i >> 2, c = i & 3;
            size_t go = (size_t)(bm + r)*K + kk + c*8;
            uint32_t d = sb + swz(r, c*16);
            CP16(d + AHO, Ah + go);
            CP16(d + ALO, Al + go);
        }
        #pragma unroll
        for (int i = tid; i < BN*4; i += 256) {
            int r = i >> 2, c = i & 3;
            size_t go = (size_t)(bn + r)*K + kk + c*8;
            CP16(sb + BO + swz(r, c*16), Bp + go);
        }
    };

    const int KB = K >> 5;
    load_stage(0, 0); CP_COMMIT();
    if (KB > 1) { load_stage(1, 1); CP_COMMIT(); }
    for (int kb = 0; kb < KB; kb++) {
        if (kb + 2 < KB)      { load_stage(kb+2, (kb+2)%3); CP_COMMIT(); CP_WAIT2(); }
        else if (kb + 1 < KB) { CP_WAIT1(); }
        else                  { CP_WAIT0(); }
        __syncthreads();
        uint32_t sb = sbase + (uint32_t)((kb % 3) * ST);
        #pragma unroll
        for (int kc = 0; kc < 2; kc++) {
            uint32_t ah[2][4], al[2][4];
            #pragma unroll
            for (int i = 0; i < 2; i++) {
                uint32_t ao = sb + swz(ra + i*16, ca + kc*32);
                ldsm4(ah[i], ao + AHO);
                ldsm4(al[i], ao + ALO);
            }
            #pragma unroll
            for (int jp = 0; jp < NP; jp++) {
                uint32_t bf[4];
                ldsm4(bf, sb + BO + swz(rb + jp*16, cb + kc*32));
                mma16h(acc[0][2*jp],   al[0], bf[0], bf[1]);
                mma16h(acc[1][2*jp],   al[1], bf[0], bf[1]);
                mma16h(acc[0][2*jp+1], al[0], bf[2], bf[3]);
                mma16h(acc[1][2*jp+1], al[1], bf[2], bf[3]);
                mma16h(acc[0][2*jp],   ah[0], bf[0], bf[1]);
                mma16h(acc[1][2*jp],   ah[1], bf[0], bf[1]);
                mma16h(acc[0][2*jp+1], ah[0], bf[2], bf[3]);
                mma16h(acc[1][2*jp+1], ah[1], bf[2], bf[3]);
            }
        }
        __syncthreads();
    }
    const int lr = lane >> 2, lc = lane & 3;
    #pragma unroll
    for (int i = 0; i < 2; i++) {
        int r = bm + m0 + i*16 + lr;
        #pragma unroll
        for (int j = 0; j < NT; j++) {
            int c = bn + n0 + j*8 + lc*2;
            float b0 = bias ? bias[c]   : 0.f;
            float b1 = bias ? bias[c+1] : 0.f;
            float2 v0 = make_float2(acc[i][j][0] + b0, acc[i][j][1] + b1);
            float2 v1 = make_float2(acc[i][j][2] + b0, acc[i][j][3] + b1);
            *(float2*)&C[(size_t)r*Nc + c]     = v0;
            *(float2*)&C[(size_t)(r+8)*Nc + c] = v1;
        }
    }
}

static constexpr int PIPE_SMEM_B128 = 3*(2*128*64 + 128*64);  // 73728
static constexpr int PIPE_SMEM_B64  = 3*(2*128*64 + 64*64);   // 61440

// ---------------- GCN aggregation: fused relu + fp16 hi/lo output ----------------
template<int XWID, int DH, int DL>
__global__ void k_gcn_gather(const float* __restrict__ bias) {
    const float* xw = gbuf<XWID>();
    uint32_t* dh = (uint32_t*)ghf<DH>();
    uint32_t* dl = (uint32_t*)ghf<DL>();
    int b = (blockIdx.x*blockDim.x + threadIdx.x) >> 5;
    if (b >= TNV) return;
    int lane = threadIdx.x & 31;
    const float4* xw4 = (const float4*)xw;
    float dv = g_dinv[b];
    float sn = dv*dv;
    float4 sv = xw4[(size_t)b*32 + lane];
    float4 acc = make_float4(sn*sv.x, sn*sv.y, sn*sv.z, sn*sv.w);
    int beg = g_offA[b], end = g_offA[b+1];
    for (int k = beg; k < end; k++) {
        int sr = g_srcA[k];
        float nm = g_normA[k];
        float4 v = xw4[(size_t)sr*32 + lane];
        acc.x += nm*v.x; acc.y += nm*v.y; acc.z += nm*v.z; acc.w += nm*v.w;
    }
    float4 bb = ((const float4*)bias)[lane];
    float r0 = fmaxf(acc.x+bb.x, 0.f), r1 = fmaxf(acc.y+bb.y, 0.f);
    float r2 = fmaxf(acc.z+bb.z, 0.f), r3 = fmaxf(acc.w+bb.w, 0.f);
    int idx = b*64 + 2*lane;
    uint2 vh = make_uint2(packhf2(r0, r1), packhf2(r2, r3));
    uint2 vl = make_uint2(packhf2(r0 - hf_hi_f(r0), r1 - hf_hi_f(r1)),
                          packhf2(r2 - hf_hi_f(r2), r3 - hf_hi_f(r3)));
    *(uint2*)&dh[idx] = vh;
    *(uint2*)&dl[idx] = vl;
}

// ---------------- attention score dots ----------------
__global__ void k_att1(const float* __restrict__ asrc, const float* __restrict__ adst) {
    const float* xw = g_xwg1;
    int w = (blockIdx.x*blockDim.x + threadIdx.x) >> 5;
    if (w >= TNV*4) return;
    int lane = threadIdx.x & 31;
    int i = w >> 2, h = w & 3;
    const float* row = xw + (size_t)i*512 + h*128;
    const float* s = asrc + h*128;
    const float* d = adst + h*128;
    float accs = 0.f, accd = 0.f;
    for (int j = lane; j < 128; j += 32) {
        float v = row[j];
        accs += v*s[j]; accd += v*d[j];
    }
    for (int o = 16; o; o >>= 1) {
        accs += __shfl_down_sync(0xffffffffu, accs, o);
        accd += __shfl_down_sync(0xffffffffu, accd, o);
    }
    if (!lane) { g_as1[w] = accs; g_ad1[w] = accd; }
}

__global__ void k_att2(const float* __restrict__ asrc, const float* __restrict__ adst) {
    const float* xw = g_xwg2;
    int w = (blockIdx.x*blockDim.x + threadIdx.x) >> 5;
    if (w >= TNV) return;
    int lane = threadIdx.x & 31;
    const float* row = xw + (size_t)w*64;
    float accs = row[lane]*asrc[lane] + row[lane+32]*asrc[lane+32];
    float accd = row[lane]*adst[lane] + row[lane+32]*adst[lane+32];
    for (int o = 16; o; o >>= 1) {
        accs += __shfl_down_sync(0xffffffffu, accs, o);
        accd += __shfl_down_sync(0xffffffffu, accd, o);
    }
    if (!lane) { g_as2[w] = accs; g_ad2[w] = accd; }
}

__device__ __forceinline__ float lrelu(float x) { return x > 0.f ? x : 0.2f*x; }

// ---------------- GAT layer-1 aggregation: fused relu + fp16 hi/lo z1 ----------------
__global__ __launch_bounds__(512)
void k_gat1_gather(const float* __restrict__ bias) {
    const float* xw = g_xwg1;
    __shared__ float red[512];
    __shared__ float p_sh[128*4];
    __shared__ int   src_sh[128];
    __shared__ float sden[4];
    int d = blockIdx.x;
    int tid = threadIdx.x;
    int h = tid >> 7, c = tid & 127;
    int beg = g_offB[d], end = g_offB[d+1];
    int nE = end - beg;
    float adh = g_ad1[d*4+h];
    float eself = lrelu(g_as1[d*4+h] + adh);
    float lmax = eself;
    for (int k = c; k < nE; k += 128) {
        int s = g_srcB[beg+k];
        lmax = fmaxf(lmax, lrelu(g_as1[s*4+h] + adh));
    }
    red[tid] = lmax; __syncthreads();
    for (int s = 64; s > 0; s >>= 1) {
        if (c < s) red[tid] = fmaxf(red[tid], red[tid+s]);
        __syncthreads();
    }
    float emax = red[h << 7];
    float pself = expf(eself - emax);
    float acc = pself * xw[(size_t)d*512 + tid];
    float ldenom = (c == 0) ? pself : 0.f;
    for (int base = 0; base < nE; base += 128) {
        int kmax = min(128, nE - base);
        __syncthreads();
        if (tid < kmax) src_sh[tid] = g_srcB[beg + base + tid];
        __syncthreads();
        if (c < kmax) {
            int s = src_sh[c];
            p_sh[c*4 + h] = expf(lrelu(g_as1[s*4+h] + adh) - emax);
        }
        __syncthreads();
        for (int kk = 0; kk < kmax; kk++) {
            float p = p_sh[kk*4 + h];
            acc += p * xw[(size_t)src_sh[kk]*512 + tid];
            if (c == 0) ldenom += p;
        }
    }
    if (c == 0) sden[h] = ldenom;
    __syncthreads();
    float o = fmaxf(acc / (sden[h] + 1e-16f) + bias[tid], 0.f);
    __half hi = __float2half_rn(o);
    h_z1h[(size_t)d*512 + tid] = hi;
    h_z1l[(size_t)d*512 + tid] = __float2half_rn(o - __half2float(hi));
}

// ---------------- GAT layer-2 aggregation ----------------
__global__ __launch_bounds__(64)
void k_gat2_gather(const float* __restrict__ bias) {
    const float* xw = g_xwg2;
    float* z = g_z2;
    __shared__ float red[64];
    __shared__ float p_sh[64];
    __shared__ int   src_sh[64];
    __shared__ float sden;
    int d = blockIdx.x;
    int tid = threadIdx.x;
    int beg = g_offB[d], end = g_offB[d+1];
    int nE = end - beg;
    float adh = g_ad2[d];
    float eself = lrelu(g_as2[d] + adh);
    float lmax = eself;
    for (int k = tid; k < nE; k += 64)
        lmax = fmaxf(lmax, lrelu(g_as2[g_srcB[beg+k]] + adh));
    red[tid] = lmax; __syncthreads();
    for (int s = 32; s > 0; s >>= 1) {
        if (tid < s) red[tid] = fmaxf(red[tid], red[tid+s]);
        __syncthreads();
    }
    float emax = red[0];
    float pself = expf(eself - emax);
    float acc = pself * xw[d*64 + tid];
    float ldenom = (tid == 0) ? pself : 0.f;
    for (int base = 0; base < nE; base += 64) {
        int kmax = min(64, nE - base);
        __syncthreads();
        if (tid < kmax) {
            int s = g_srcB[beg + base + tid];
            src_sh[tid] = s;
            p_sh[tid] = expf(lrelu(g_as2[s] + adh) - emax);
        }
        __syncthreads();
        for (int kk = 0; kk < kmax; kk++) {
            float p = p_sh[kk];
            acc += p * xw[src_sh[kk]*64 + tid];
            if (tid == 0) ldenom += p;
        }
    }
    if (tid == 0) sden = ldenom;
    __syncthreads();
    z[d*64 + tid] = acc / (sden + 1e-16f) + bias[tid];
}

// ---------------- self-loop-only nodes ----------------
__global__ void k_zrest1(const float* __restrict__ bias) {
    int i = blockIdx.x*blockDim.x + threadIdx.x;
    if (i >= (TNV-NN)*512) return;
    size_t off = (size_t)NN*512 + i;
    float o = fmaxf(g_xwg1[off] + bias[i & 511], 0.f);
    __half hi = __float2half_rn(o);
    h_z1h[off] = hi;
    h_z1l[off] = __float2half_rn(o - __half2float(hi));
}
__global__ void k_zrest2(const float* __restrict__ bias) {
    int i = blockIdx.x*blockDim.x + threadIdx.x;
    if (i >= (TNV-NN)*64) return;
    int off = NN*64 + i;
    g_z2[off] = g_xwg2[off] + bias[i & 63];
}

// ---------------- link prediction ----------------
__global__ void k_link(const int* __restrict__ eli, float* __restrict__ out) {
    const float* z = g_z2;
    int w = (blockIdx.x*blockDim.x + threadIdx.x) >> 5;
    if (w >= ELN) return;
    int lane = threadIdx.x & 31;
    int u = eli[w] & (TNV-1);
    int v = eli[ELN + w] & (TNV-1);
    float s = z[u*64+lane]*z[v*64+lane] + z[u*64+lane+32]*z[v*64+lane+32];
    for (int o = 16; o; o >>= 1) s += __shfl_down_sync(0xffffffffu, s, o);
    if (!lane) out[w] = s;
}

// ---------------- launch: two-stream fork/join ----------------
extern "C" void kernel_launch(void* const* d_in, const int* in_sizes, int n_in,
                              void* d_out, int out_size) {
    const float* x    = (const float*)d_in[0];
    const int*   ei   = (const int*)d_in[1];
    const float* ea   = (const float*)d_in[2];
    const int*   eli  = (const int*)d_in[3];
    const float* c1w = (const float*)d_in[4];
    const float* c1b = (const float*)d_in[5];
    const float* c2w = (const float*)d_in[6];
    const float* c2b = (const float*)d_in[7];
    const float* g1w = (const float*)d_in[8];
    const float* g1as = (const float*)d_in[9];
    const float* g1ad = (const float*)d_in[10];
    const float* g1b = (const float*)d_in[11];
    const float* g2w = (const float*)d_in[12];
    const float* g2as = (const float*)d_in[13];
    const float* g2ad = (const float*)d_in[14];
    const float* g2b = (const float*)d_in[15];
    const float* fcw = (const float*)d_in[16];
    const float* fcb = (const float*)d_in[17];

    float* out  = (float*)d_out;
    float* link = out;
    float* hop  = out + ELN;

    static cudaStream_t s1 = nullptr, s2 = nullptr;
    static cudaEvent_t evCvt2 = nullptr, evCvt1 = nullptr, evGraph = nullptr, evJ1 = nullptr, evJ2 = nullptr;
    if (!s1) {
        cudaStreamCreateWithFlags(&s1, cudaStreamNonBlocking);
        cudaStreamCreateWithFlags(&s2, cudaStreamNonBlocking);
        cudaEventCreateWithFlags(&evCvt2,  cudaEventDisableTiming);
        cudaEventCreateWithFlags(&evCvt1,  cudaEventDisableTiming);
        cudaEventCreateWithFlags(&evGraph, cudaEventDisableTiming);
        cudaEventCreateWithFlags(&evJ1,    cudaEventDisableTiming);
        cudaEventCreateWithFlags(&evJ2,    cudaEventDisableTiming);
        cudaFuncSetAttribute(mma_pipe_a2b1<128, HF_XH,HF_XL,HF_G1W, BUF_XWG1>, cudaFuncAttributeMaxDynamicSharedMemorySize, PIPE_SMEM_B128);
        cudaFuncSetAttribute(mma_pipe_a2b1<128, HF_XH,HF_XL,HF_C1W, BUF_XW1>,  cudaFuncAttributeMaxDynamicSharedMemorySize, PIPE_SMEM_B128);
        cudaFuncSetAttribute(mma_pipe_a2b1<128, HF_H1H,HF_H1L,HF_C2W, BUF_XW2>, cudaFuncAttributeMaxDynamicSharedMemorySize, PIPE_SMEM_B128);
        cudaFuncSetAttribute(mma_pipe_a2b1<128, HF_H2H,HF_H2L,HF_WF, BUF_EXT>, cudaFuncAttributeMaxDynamicSharedMemorySize, PIPE_SMEM_B128);
        cudaFuncSetAttribute(mma_pipe_a2b1<64,  HF_Z1H,HF_Z1L,HF_G2W, BUF_XWG2>, cudaFuncAttributeMaxDynamicSharedMemorySize, PIPE_SMEM_B64);
    }

    // ---- main stream head: conversions for stream-2's first GEMM ----
    k_init<<<TNV/256, 256>>>();                                                   // 0
    k_cvt_hl<HF_XH, HF_XL><<<(TNV*DIN/4 + 255)/256, 256>>>(x, TNV*DIN/4);         // 1
    k_cvt_w<HF_G1W><<<(512*DIN/4 + 255)/256, 256>>>(g1w, 512*DIN/4);              // 2
    cudaEventRecord(evCvt2, 0);

    // ---- stream 2 head (slot 3 for ncu visibility) ----
    cudaStreamWaitEvent(s2, evCvt2, 0);
    mma_pipe_a2b1<128, HF_XH,HF_XL,HF_G1W, BUF_XWG1>
        <<<dim3(512/128, TNV/128), 256, PIPE_SMEM_B128, s2>>>(nullptr, nullptr, TNV, 512, DIN); // 3
    k_att1<<<TNV, 128, 0, s2>>>(g1as, g1ad);                                      // 4

    // ---- main stream: rest of conversions + graph build ----
    k_cvt_w<HF_C1W><<<(HID*DIN/4 + 255)/256, 256>>>(c1w, HID*DIN/4);
    cudaEventRecord(evCvt1, 0);
    k_hist<<<TEV/256, 256>>>(ei, ea);
    k_scanA<<<1, 1024>>>();
    k_scanB<<<1, 1024>>>();
    k_dinv<<<TNV/256, 256>>>();
    k_fill<<<TEV/256, 256>>>(ei, ea);
    k_weff_f16<<<(NN*HID/2 + 255)/256, 256>>>(fcw);
    k_cvt_w<HF_C2W><<<(HID*HID/4 + 255)/256, 256>>>(c2w, HID*HID/4);
    k_cvt_w<HF_G2W><<<(64*512/4 + 255)/256, 256>>>(g2w, 64*512/4);
    cudaEventRecord(evGraph, 0);

    // ---- stream 1: GCN hop branch ----
    cudaStreamWaitEvent(s1, evCvt1, 0);
    mma_pipe_a2b1<128, HF_XH,HF_XL,HF_C1W, BUF_XW1>
        <<<dim3(1, TNV/128), 256, PIPE_SMEM_B128, s1>>>(nullptr, nullptr, TNV, 128, DIN);
    cudaStreamWaitEvent(s1, evGraph, 0);
    k_gcn_gather<BUF_XW1, HF_H1H, HF_H1L><<<TNV/4, 128, 0, s1>>>(c1b);
    mma_pipe_a2b1<128, HF_H1H,HF_H1L,HF_C2W, BUF_XW2>
        <<<dim3(1, TNV/128), 256, PIPE_SMEM_B128, s1>>>(nullptr, nullptr, TNV, 128, HID);
    k_gcn_gather<BUF_XW2, HF_H2H, HF_H2L><<<TNV/4, 128, 0, s1>>>(c2b);
    mma_pipe_a2b1<128, HF_H2H,HF_H2L,HF_WF, BUF_EXT>
        <<<dim3(NN/128, TNV/128), 256, PIPE_SMEM_B128, s1>>>(fcb, hop, TNV, NN, HID);
    cudaEventRecord(evJ1, s1);

    // ---- stream 2 tail: GAT link branch ----
    cudaStreamWaitEvent(s2, evGraph, 0);
    k_gat1_gather<<<NN, 512, 0, s2>>>(g1b);
    k_zrest1<<<((TNV-NN)*512)/256, 256, 0, s2>>>(g1b);
    mma_pipe_a2b1<64, HF_Z1H,HF_Z1L,HF_G2W, BUF_XWG2>
        <<<dim3(1, TNV/128), 256, PIPE_SMEM_B64, s2>>>(nullptr, nullptr, TNV, 64, 512);
    k_att2<<<TNV/4, 128, 0, s2>>>(g2as, g2ad);
    k_gat2_gather<<<NN, 64, 0, s2>>>(g2b);
    k_zrest2<<<((TNV-NN)*64)/256, 256, 0, s2>>>(g2b);
    k_link<<<ELN/4, 128, 0, s2>>>(eli, link);
    cudaEventRecord(evJ2, s2);

    // ---- join ----
    cudaStreamWaitEvent(0, evJ1, 0);
    cudaStreamWaitEvent(0, evJ2, 0);
}

// round 17
// speedup vs baseline: 1.5878x; 1.5878x over previous
#include <cuda_runtime.h>
#include <cuda_bf16.h>
#include <cuda_fp16.h>
#include <math.h>
#include <stdint.h>

#define TT   16
#define NN   2048
#define EE   16384
#define ELN  8192
#define TNV  (TT*NN)   /* 32768 */
#define TEV  (TT*EE)   /* 262144 */
#define HID  128
#define DIN  64

// ---------------- fp32 scratch ----------------
__device__ float g_deg[TNV];
__device__ float g_dinv[TNV];
__device__ int   g_cntA[TNV];
__device__ int   g_offA[TNV+1];
__device__ int   g_curA[TNV];
__device__ int   g_cntB[NN];
__device__ int   g_offB[NN+1];
__device__ int   g_curB[NN];
__device__ int   g_srcA[TEV];
__device__ float g_normA[TEV];
__device__ int   g_srcB[TEV];

__device__ __align__(16) float g_xw1[TNV*HID];
__device__ __align__(16) float g_xw2[TNV*HID];

__device__ __align__(16) float g_xwg1[(size_t)TNV*512];
__device__ float g_as1[TNV*4];
__device__ float g_ad1[TNV*4];
__device__ __align__(16) float g_xwg2[TNV*64];
__device__ float g_as2[TNV];
__device__ float g_ad2[TNV];
__device__ __align__(16) float g_z2 [TNV*64];

#define BUF_EXT   (-1)
#define BUF_XW1   0
#define BUF_XW2   2
#define BUF_XWG1  5
#define BUF_XWG2  7

template<int ID>
__device__ __forceinline__ float* gbuf() {
    if (ID == BUF_XW1)  return g_xw1;
    if (ID == BUF_XW2)  return g_xw2;
    if (ID == BUF_XWG1) return g_xwg1;
    if (ID == BUF_XWG2) return g_xwg2;
    return nullptr;
}

// ---------------- 16-bit operand buffers ----------------
__device__ __align__(16) __nv_bfloat16 b_xh [TNV*DIN];
__device__ __align__(16) __nv_bfloat16 b_xl [TNV*DIN];
__device__ __align__(16) __nv_bfloat16 b_h1h[TNV*HID];
__device__ __align__(16) __nv_bfloat16 b_h1l[TNV*HID];
__device__ __align__(16) __nv_bfloat16 b_h2h[TNV*HID];   // fp16 hi
__device__ __align__(16) __nv_bfloat16 b_h2l[TNV*HID];   // fp16 lo
__device__ __align__(16) __nv_bfloat16 b_z1h[(size_t)TNV*512];
__device__ __align__(16) __nv_bfloat16 b_z1l[(size_t)TNV*512];
__device__ __align__(16) __nv_bfloat16 b_c1wh[HID*DIN];
__device__ __align__(16) __nv_bfloat16 b_c1wl[HID*DIN];
__device__ __align__(16) __nv_bfloat16 b_c2wh[HID*HID];
__device__ __align__(16) __nv_bfloat16 b_c2wl[HID*HID];
__device__ __align__(16) __nv_bfloat16 b_g1wh[512*DIN];
__device__ __align__(16) __nv_bfloat16 b_g1wl[512*DIN];
__device__ __align__(16) __nv_bfloat16 b_g2wh[64*512];
__device__ __align__(16) __nv_bfloat16 b_g2wl[64*512];
__device__ __align__(16) __nv_bfloat16 b_wf  [NN*HID];   // weff single fp16

#define BF_XH 0
#define BF_XL 1
#define BF_H1H 2
#define BF_H1L 3
#define BF_H2H 4
#define BF_H2L 5
#define BF_Z1H 6
#define BF_Z1L 7
#define BF_C1WH 8
#define BF_C1WL 9
#define BF_C2WH 10
#define BF_C2WL 11
#define BF_G1WH 14
#define BF_G1WL 15
#define BF_G2WH 16
#define BF_G2WL 17
#define BF_WF   18

template<int ID>
__device__ __forceinline__ __nv_bfloat16* gbf() {
    if (ID == BF_XH)  return b_xh;
    if (ID == BF_XL)  return b_xl;
    if (ID == BF_H1H) return b_h1h;
    if (ID == BF_H1L) return b_h1l;
    if (ID == BF_H2H) return b_h2h;
    if (ID == BF_H2L) return b_h2l;
    if (ID == BF_Z1H) return b_z1h;
    if (ID == BF_Z1L) return b_z1l;
    if (ID == BF_C1WH) return b_c1wh;
    if (ID == BF_C1WL) return b_c1wl;
    if (ID == BF_C2WH) return b_c2wh;
    if (ID == BF_C2WL) return b_c2wl;
    if (ID == BF_G1WH) return b_g1wh;
    if (ID == BF_G1WL) return b_g1wl;
    if (ID == BF_G2WH) return b_g2wh;
    if (ID == BF_G2WL) return b_g2wl;
    if (ID == BF_WF)   return b_wf;
    return nullptr;
}

// ---------------- helpers ----------------
__device__ __forceinline__ uint32_t packbf2(float e0, float e1) {
    uint32_t a = (uint32_t)__bfloat16_as_ushort(__float2bfloat16_rn(e0));
    uint32_t b = (uint32_t)__bfloat16_as_ushort(__float2bfloat16_rn(e1));
    return (b << 16) | a;
}
__device__ __forceinline__ float bf_hi_f(float x) {
    return __bfloat162float(__float2bfloat16_rn(x));
}
__device__ __forceinline__ uint32_t packhf2(float e0, float e1) {
    uint32_t a = (uint32_t)__half_as_ushort(__float2half_rn(e0));
    uint32_t b = (uint32_t)__half_as_ushort(__float2half_rn(e1));
    return (b << 16) | a;
}
__device__ __forceinline__ float hf_hi_f(float x) {
    return __half2float(__float2half_rn(x));
}

// ---------------- setup kernels ----------------
__global__ void k_init() {
    int i = blockIdx.x*blockDim.x + threadIdx.x;
    if (i < TNV) { g_deg[i]=0.f; g_cntA[i]=0; g_curA[i]=0; }
    if (i < NN)  { g_cntB[i]=0; g_curB[i]=0; }
}

__global__ void k_hist(const int* __restrict__ ei, const float* __restrict__ ea) {
    int idx = blockIdx.x*blockDim.x + threadIdx.x;
    if (idx >= TEV) return;
    int t = idx >> 14, e = idx & (EE-1);
    int dst = ei[(t*2+1)*EE + e] & (NN-1);
    float w = ea[idx];
    atomicAdd(&g_deg[t*NN+dst], w);
    atomicAdd(&g_cntA[t*NN+dst], 1);
    atomicAdd(&g_cntB[dst], 1);
}

__device__ void scan_impl(const int* cnt, int* off, int n) {
    __shared__ int part[1024];
    int tid = threadIdx.x;
    int per = n / 1024;
    int base = tid * per;
    int s = 0;
    for (int i = 0; i < per; i++) s += cnt[base+i];
    part[tid] = s; __syncthreads();
    for (int d = 1; d < 1024; d <<= 1) {
        int v = (tid >= d) ? part[tid-d] : 0;
        __syncthreads();
        part[tid] += v;
        __syncthreads();
    }
    int run = (tid == 0) ? 0 : part[tid-1];
    for (int i = 0; i < per; i++) { off[base+i] = run; run += cnt[base+i]; }
    if (tid == 1023) off[n] = run;
}
__global__ void k_scanA() { scan_impl(g_cntA, g_offA, TNV); }
__global__ void k_scanB() { scan_impl(g_cntB, g_offB, NN); }

__global__ void k_dinv() {
    int i = blockIdx.x*blockDim.x + threadIdx.x;
    if (i < TNV) g_dinv[i] = 1.0f / sqrtf(g_deg[i] + 1.0f);
}

__global__ void k_fill(const int* __restrict__ ei, const float* __restrict__ ea) {
    int idx = blockIdx.x*blockDim.x + threadIdx.x;
    if (idx >= TEV) return;
    int t = idx >> 14, e = idx & (EE-1);
    int src = ei[(t*2  )*EE + e] & (NN-1);
    int dst = ei[(t*2+1)*EE + e] & (NN-1);
    float w = ea[idx];
    float nm = g_dinv[t*NN+src] * w * g_dinv[t*NN+dst];
    int bA = t*NN + dst;
    int p = atomicAdd(&g_curA[bA], 1);
    int slot = g_offA[bA] + p;
    g_srcA[slot] = t*NN + src;
    g_normA[slot] = nm;
    int q = atomicAdd(&g_curB[dst], 1);
    g_srcB[g_offB[dst] + q] = src;
}

// weff = W[:, :128] + W[:, 128:], emitted directly as single fp16
__global__ void k_weff_f16(const float* __restrict__ fcw) {
    int i = blockIdx.x*blockDim.x + threadIdx.x;   // u32 pair index
    if (i >= NN*HID/2) return;
    int e = 2*i;
    int r = e >> 7, c = e & 127;
    float v0 = fcw[r*256 + c]     + fcw[r*256 + 128 + c];
    float v1 = fcw[r*256 + c + 1] + fcw[r*256 + 128 + c + 1];
    ((uint32_t*)b_wf)[i] = packhf2(v0, v1);
}

// ---------------- fp32 -> bf16 hi/lo conversion ----------------
template<int SRCID, int DH, int DL>
__global__ void k_cvt(const float* __restrict__ srcExt, int n4) {
    const float* src = (SRCID < 0) ? srcExt : gbuf<SRCID>();
    uint32_t* dh = (uint32_t*)gbf<DH>();
    uint32_t* dl = (uint32_t*)gbf<DL>();
    int i = blockIdx.x*blockDim.x + threadIdx.x;
    if (i >= n4) return;
    float4 v = ((const float4*)src)[i];
    dh[2*i]   = packbf2(v.x, v.y);
    dh[2*i+1] = packbf2(v.z, v.w);
    dl[2*i]   = packbf2(v.x - bf_hi_f(v.x), v.y - bf_hi_f(v.y));
    dl[2*i+1] = packbf2(v.z - bf_hi_f(v.z), v.w - bf_hi_f(v.w));
}

// ======= GEMM core pieces (3-stage cp.async ring + XOR-swizzled 64B rows) =======
__device__ __forceinline__ void mma16(float* c, const uint32_t* a, uint32_t b0, uint32_t b1) {
    asm volatile("mma.sync.aligned.m16n8k16.row.col.f32.bf16.bf16.f32 "
                 "{%0,%1,%2,%3}, {%4,%5,%6,%7}, {%8,%9}, {%0,%1,%2,%3};"
                 : "+f"(c[0]), "+f"(c[1]), "+f"(c[2]), "+f"(c[3])
                 : "r"(a[0]), "r"(a[1]), "r"(a[2]), "r"(a[3]), "r"(b0), "r"(b1));
}
__device__ __forceinline__ void mma16h(float* c, const uint32_t* a, uint32_t b0, uint32_t b1) {
    asm volatile("mma.sync.aligned.m16n8k16.row.col.f32.f16.f16.f32 "
                 "{%0,%1,%2,%3}, {%4,%5,%6,%7}, {%8,%9}, {%0,%1,%2,%3};"
                 : "+f"(c[0]), "+f"(c[1]), "+f"(c[2]), "+f"(c[3])
                 : "r"(a[0]), "r"(a[1]), "r"(a[2]), "r"(a[3]), "r"(b0), "r"(b1));
}
__device__ __forceinline__ void ldsm4(uint32_t* r, uint32_t a) {
    asm volatile("ldmatrix.sync.aligned.m8n8.x4.shared.b16 {%0,%1,%2,%3}, [%4];"
                 : "=r"(r[0]), "=r"(r[1]), "=r"(r[2]), "=r"(r[3]) : "r"(a));
}
#define CP16(dst, src) asm volatile("cp.async.cg.shared.global [%0], [%1], 16;" :: "r"(dst), "l"(src) : "memory")
#define CP_COMMIT()    asm volatile("cp.async.commit_group;" ::: "memory")
#define CP_WAIT2()     asm volatile("cp.async.wait_group 2;" ::: "memory")
#define CP_WAIT1()     asm volatile("cp.async.wait_group 1;" ::: "memory")
#define CP_WAIT0()     asm volatile("cp.async.wait_group 0;" ::: "memory")

__device__ __forceinline__ uint32_t swz(int r, int cbyte) {
    return (uint32_t)(r*64 + ((((cbyte >> 4) ^ ((r >> 1) & 3)) & 3) << 4));
}

// ---- bf16 3-term GEMM (A hi/lo, B hi/lo); optional fused attention dots ----
// ATT: 0 = none; 1 = gat1 (4 heads of 128 cols -> g_as1/g_ad1); 2 = gat2 (1 head of 64 -> g_as2/g_ad2)
template<int BN, int AH_, int AL_, int BH_, int BL_, int CID, int ATT>
__global__ __launch_bounds__(256, 2)
void mma_pipe(const float* __restrict__ bias, const float* __restrict__ asrc,
              const float* __restrict__ adst, float* __restrict__ Cext,
              int M, int Nc, int K) {
    extern __shared__ char smem[];
    constexpr int TILE_A = 128*64;
    constexpr int TILE_B = BN*64;
    constexpr int ST  = 2*TILE_A + 2*TILE_B;
    constexpr int AHO = 0, ALO = TILE_A, BHO = 2*TILE_A, BLO = 2*TILE_A + TILE_B;
    constexpr int WN = BN/2, NT = WN/8, NP = NT/2;

    const __nv_bfloat16* Ah = gbf<AH_>();
    const __nv_bfloat16* Al = gbf<AL_>();
    const __nv_bfloat16* Bh = gbf<BH_>();
    const __nv_bfloat16* Bl = gbf<BL_>();
    float* C = (CID < 0) ? Cext : gbuf<CID>();

    const int tid = threadIdx.x;
    const int wid = tid >> 5, lane = tid & 31;
    const int wr = wid & 3, wc = wid >> 2;
    const int m0 = wr * 32, n0 = wc * WN;
    const int bm = blockIdx.y * 128, bn = blockIdx.x * BN;
    const int g = lane >> 3, lr8 = lane & 7;
    const int ra = m0 + (g & 1)*8 + lr8;  const int ca = (g >> 1) * 16;
    const int rb = n0 + (g >> 1)*8 + lr8; const int cb = (g & 1) * 16;
    uint32_t sbase = (uint32_t)__cvta_generic_to_shared(smem);

    float acc[2][NT][4];
    #pragma unroll
    for (int i = 0; i < 2; i++)
        #pragma unroll
        for (int j = 0; j < NT; j++)
            #pragma unroll
            for (int q = 0; q < 4; q++) acc[i][j][q] = 0.f;

    auto load_stage = [&](int kb, int s) {
        const int kk = kb * 32;
        uint32_t sb = sbase + s*ST;
        #pragma unroll
        for (int i = tid; i < 128*4; i += 256) {
            int r = i >> 2, c = i & 3;
            size_t go = (size_t)(bm + r)*K + kk + c*8;
            uint32_t d = sb + swz(r, c*16);
            CP16(d + AHO, Ah + go);
            CP16(d + ALO, Al + go);
        }
        #pragma unroll
        for (int i = tid; i < BN*4; i += 256) {
            int r = i >> 2, c = i & 3;
            size_t go = (size_t)(bn + r)*K + kk + c*8;
            uint32_t d = sb + swz(r, c*16);
            CP16(d + BHO, Bh + go);
            CP16(d + BLO, Bl + go);
        }
    };

    const int KB = K >> 5;
    load_stage(0, 0); CP_COMMIT();
    if (KB > 1) { load_stage(1, 1); CP_COMMIT(); }
    for (int kb = 0; kb < KB; kb++) {
        if (kb + 2 < KB)      { load_stage(kb+2, (kb+2)%3); CP_COMMIT(); CP_WAIT2(); }
        else if (kb + 1 < KB) { CP_WAIT1(); }
        else                  { CP_WAIT0(); }
        __syncthreads();
        uint32_t sb = sbase + (uint32_t)((kb % 3) * ST);
        #pragma unroll
        for (int kc = 0; kc < 2; kc++) {
            uint32_t ah[2][4], al[2][4];
            #pragma unroll
            for (int i = 0; i < 2; i++) {
                uint32_t ao = sb + swz(ra + i*16, ca + kc*32);
                ldsm4(ah[i], ao + AHO);
                ldsm4(al[i], ao + ALO);
            }
            #pragma unroll
            for (int jp = 0; jp < NP; jp++) {
                uint32_t bh[4], bl[4];
                uint32_t bo = sb + swz(rb + jp*16, cb + kc*32);
                ldsm4(bh, bo + BHO);
                ldsm4(bl, bo + BLO);
                mma16(acc[0][2*jp],   al[0], bh[0], bh[1]);
                mma16(acc[1][2*jp],   al[1], bh[0], bh[1]);
                mma16(acc[0][2*jp+1], al[0], bh[2], bh[3]);
                mma16(acc[1][2*jp+1], al[1], bh[2], bh[3]);
                mma16(acc[0][2*jp],   ah[0], bl[0], bl[1]);
                mma16(acc[1][2*jp],   ah[1], bl[0], bl[1]);
                mma16(acc[0][2*jp+1], ah[0], bl[2], bl[3]);
                mma16(acc[1][2*jp+1], ah[1], bl[2], bl[3]);
                mma16(acc[0][2*jp],   ah[0], bh[0], bh[1]);
                mma16(acc[1][2*jp],   ah[1], bh[0], bh[1]);
                mma16(acc[0][2*jp+1], ah[0], bh[2], bh[3]);
                mma16(acc[1][2*jp+1], ah[1], bh[2], bh[3]);
            }
        }
        __syncthreads();
    }
    const int lr = lane >> 2, lc = lane & 3;
    #pragma unroll
    for (int i = 0; i < 2; i++) {
        int r = bm + m0 + i*16 + lr;
        #pragma unroll
        for (int j = 0; j < NT; j++) {
            int c = bn + n0 + j*8 + lc*2;
            float b0 = bias ? bias[c]   : 0.f;
            float b1 = bias ? bias[c+1] : 0.f;
            float2 v0 = make_float2(acc[i][j][0] + b0, acc[i][j][1] + b1);
            float2 v1 = make_float2(acc[i][j][2] + b0, acc[i][j][3] + b1);
            *(float2*)&C[(size_t)r*Nc + c]     = v0;
            *(float2*)&C[(size_t)(r+8)*Nc + c] = v1;
        }
    }
    if (ATT != 0) {
        // fused attention dot: block's col range is exactly one head
        float* s_as = (float*)smem;
        float* s_ad = (float*)smem + 128;
        if (tid < 128) { s_as[tid] = 0.f; s_ad[tid] = 0.f; }
        __syncthreads();
        float ps[2] = {0.f, 0.f}, ps8[2] = {0.f, 0.f};
        float pd[2] = {0.f, 0.f}, pd8[2] = {0.f, 0.f};
        #pragma unroll
        for (int i = 0; i < 2; i++)
            #pragma unroll
            for (int j = 0; j < NT; j++) {
                int c = bn + n0 + j*8 + lc*2;
                float a0 = asrc[c], a1 = asrc[c+1];
                float d0 = adst[c], d1 = adst[c+1];
                ps[i]  += acc[i][j][0]*a0 + acc[i][j][1]*a1;
                ps8[i] += acc[i][j][2]*a0 + acc[i][j][3]*a1;
                pd[i]  += acc[i][j][0]*d0 + acc[i][j][1]*d1;
                pd8[i] += acc[i][j][2]*d0 + acc[i][j][3]*d1;
            }
        #pragma unroll
        for (int o = 1; o < 4; o <<= 1) {
            #pragma unroll
            for (int i = 0; i < 2; i++) {
                ps[i]  += __shfl_xor_sync(0xffffffffu, ps[i],  o);
                ps8[i] += __shfl_xor_sync(0xffffffffu, ps8[i], o);
                pd[i]  += __shfl_xor_sync(0xffffffffu, pd[i],  o);
                pd8[i] += __shfl_xor_sync(0xffffffffu, pd8[i], o);
            }
        }
        if (lc == 0) {
            #pragma unroll
            for (int i = 0; i < 2; i++) {
                atomicAdd(&s_as[m0 + i*16 + lr],     ps[i]);
                atomicAdd(&s_as[m0 + i*16 + lr + 8], ps8[i]);
                atomicAdd(&s_ad[m0 + i*16 + lr],     pd[i]);
                atomicAdd(&s_ad[m0 + i*16 + lr + 8], pd8[i]);
            }
        }
        __syncthreads();
        if (tid < 128) {
            int node = bm + tid;
            if (ATT == 1) {
                int h = bn >> 7;
                g_as1[node*4 + h] = s_as[tid];
                g_ad1[node*4 + h] = s_ad[tid];
            } else {
                g_as2[node] = s_as[tid];
                g_ad2[node] = s_ad[tid];
            }
        }
    }
}

// ---- fp16 2-term GEMM (A hi/lo fp16, B single fp16) — hop GEMM only ----
template<int BN, int AH_, int AL_, int B_, int CID>
__global__ __launch_bounds__(256, 2)
void mma_pipe_a2b1(const float* __restrict__ bias, float* __restrict__ Cext,
                   int M, int Nc, int K) {
    extern __shared__ char smem[];
    constexpr int TILE_A = 128*64;
    constexpr int TILE_B = BN*64;
    constexpr int ST  = 2*TILE_A + TILE_B;
    constexpr int AHO = 0, ALO = TILE_A, BO = 2*TILE_A;
    constexpr int WN = BN/2, NT = WN/8, NP = NT/2;

    const __nv_bfloat16* Ah = gbf<AH_>();
    const __nv_bfloat16* Al = gbf<AL_>();
    const __nv_bfloat16* Bp = gbf<B_>();
    float* C = (CID < 0) ? Cext : gbuf<CID>();

    const int tid = threadIdx.x;
    const int wid = tid >> 5, lane = tid & 31;
    const int wr = wid & 3, wc = wid >> 2;
    const int m0 = wr * 32, n0 = wc * WN;
    const int bm = blockIdx.y * 128, bn = blockIdx.x * BN;
    const int g = lane >> 3, lr8 = lane & 7;
    const int ra = m0 + (g & 1)*8 + lr8;  const int ca = (g >> 1) * 16;
    const int rb = n0 + (g >> 1)*8 + lr8; const int cb = (g & 1) * 16;
    uint32_t sbase = (uint32_t)__cvta_generic_to_shared(smem);

    float acc[2][NT][4];
    #pragma unroll
    for (int i = 0; i < 2; i++)
        #pragma unroll
        for (int j = 0; j < NT; j++)
            #pragma unroll
            for (int q = 0; q < 4; q++) acc[i][j][q] = 0.f;

    auto load_stage = [&](int kb, int s) {
        const int kk = kb * 32;
        uint32_t sb = sbase + s*ST;
        #pragma unroll
        for (int i = tid; i < 128*4; i += 256) {
            int r = i >> 2, c = i & 3;
            size_t go = (size_t)(bm + r)*K + kk + c*8;
            uint32_t d = sb + swz(r, c*16);
            CP16(d + AHO, Ah + go);
            CP16(d + ALO, Al + go);
        }
        #pragma unroll
        for (int i = tid; i < BN*4; i += 256) {
            int r = i >> 2, c = i & 3;
            size_t go = (size_t)(bn + r)*K + kk + c*8;
            CP16(sb + BO + swz(r, c*16), Bp + go);
        }
    };

    const int KB = K >> 5;
    load_stage(0, 0); CP_COMMIT();
    if (KB > 1) { load_stage(1, 1); CP_COMMIT(); }
    for (int kb = 0; kb < KB; kb++) {
        if (kb + 2 < KB)      { load_stage(kb+2, (kb+2)%3); CP_COMMIT(); CP_WAIT2(); }
        else if (kb + 1 < KB) { CP_WAIT1(); }
        else                  { CP_WAIT0(); }
        __syncthreads();
        uint32_t sb = sbase + (uint32_t)((kb % 3) * ST);
        #pragma unroll
        for (int kc = 0; kc < 2; kc++) {
            uint32_t ah[2][4], al[2][4];
            #pragma unroll
            for (int i = 0; i < 2; i++) {
                uint32_t ao = sb + swz(ra + i*16, ca + kc*32);
                ldsm4(ah[i], ao + AHO);
                ldsm4(al[i], ao + ALO);
            }
            #pragma unroll
            for (int jp = 0; jp < NP; jp++) {
                uint32_t bf[4];
                ldsm4(bf, sb + BO + swz(rb + jp*16, cb + kc*32));
                mma16h(acc[0][2*jp],   al[0], bf[0], bf[1]);
                mma16h(acc[1][2*jp],   al[1], bf[0], bf[1]);
                mma16h(acc[0][2*jp+1], al[0], bf[2], bf[3]);
                mma16h(acc[1][2*jp+1], al[1], bf[2], bf[3]);
                mma16h(acc[0][2*jp],   ah[0], bf[0], bf[1]);
                mma16h(acc[1][2*jp],   ah[1], bf[0], bf[1]);
                mma16h(acc[0][2*jp+1], ah[0], bf[2], bf[3]);
                mma16h(acc[1][2*jp+1], ah[1], bf[2], bf[3]);
            }
        }
        __syncthreads();
    }
    const int lr = lane >> 2, lc = lane & 3;
    #pragma unroll
    for (int i = 0; i < 2; i++) {
        int r = bm + m0 + i*16 + lr;
        #pragma unroll
        for (int j = 0; j < NT; j++) {
            int c = bn + n0 + j*8 + lc*2;
            float b0 = bias ? bias[c]   : 0.f;
            float b1 = bias ? bias[c+1] : 0.f;
            float2 v0 = make_float2(acc[i][j][0] + b0, acc[i][j][1] + b1);
            float2 v1 = make_float2(acc[i][j][2] + b0, acc[i][j][3] + b1);
            *(float2*)&C[(size_t)r*Nc + c]     = v0;
            *(float2*)&C[(size_t)(r+8)*Nc + c] = v1;
        }
    }
}

static constexpr int PIPE_SMEM_128  = 3*(2*128*64 + 2*128*64);  // 98304
static constexpr int PIPE_SMEM_64   = 3*(2*128*64 + 2*64*64);   // 73728
static constexpr int PIPE_SMEM_A2B1 = 3*(2*128*64 + 128*64);    // 73728

// ---------------- GCN aggregation: fused relu + hi/lo output (FMT 0=bf16, 1=fp16) ----------------
template<int XWID, int DH, int DL, int FMT>
__global__ void k_gcn_gather(const float* __restrict__ bias) {
    const float* xw = gbuf<XWID>();
    uint32_t* dh = (uint32_t*)gbf<DH>();
    uint32_t* dl = (uint32_t*)gbf<DL>();
    int b = (blockIdx.x*blockDim.x + threadIdx.x) >> 5;
    if (b >= TNV) return;
    int lane = threadIdx.x & 31;
    const float4* xw4 = (const float4*)xw;
    float dv = g_dinv[b];
    float sn = dv*dv;
    float4 sv = xw4[(size_t)b*32 + lane];
    float4 acc = make_float4(sn*sv.x, sn*sv.y, sn*sv.z, sn*sv.w);
    int beg = g_offA[b], end = g_offA[b+1];
    for (int k = beg; k < end; k++) {
        int sr = g_srcA[k];
        float nm = g_normA[k];
        float4 v = xw4[(size_t)sr*32 + lane];
        acc.x += nm*v.x; acc.y += nm*v.y; acc.z += nm*v.z; acc.w += nm*v.w;
    }
    float4 bb = ((const float4*)bias)[lane];
    float r0 = fmaxf(acc.x+bb.x, 0.f), r1 = fmaxf(acc.y+bb.y, 0.f);
    float r2 = fmaxf(acc.z+bb.z, 0.f), r3 = fmaxf(acc.w+bb.w, 0.f);
    int idx = b*64 + 2*lane;
    uint2 vh, vl;
    if (FMT == 0) {
        vh = make_uint2(packbf2(r0, r1), packbf2(r2, r3));
        vl = make_uint2(packbf2(r0 - bf_hi_f(r0), r1 - bf_hi_f(r1)),
                        packbf2(r2 - bf_hi_f(r2), r3 - bf_hi_f(r3)));
    } else {
        vh = make_uint2(packhf2(r0, r1), packhf2(r2, r3));
        vl = make_uint2(packhf2(r0 - hf_hi_f(r0), r1 - hf_hi_f(r1)),
                        packhf2(r2 - hf_hi_f(r2), r3 - hf_hi_f(r3)));
    }
    *(uint2*)&dh[idx] = vh;
    *(uint2*)&dl[idx] = vl;
}

__device__ __forceinline__ float lrelu(float x) { return x > 0.f ? x : 0.2f*x; }

// ---------------- GAT layer-1 aggregation: fused relu + bf16 hi/lo z1 ----------------
__global__ __launch_bounds__(512)
void k_gat1_gather(const float* __restrict__ bias) {
    const float* xw = g_xwg1;
    __shared__ float red[512];
    __shared__ float p_sh[128*4];
    __shared__ int   src_sh[128];
    __shared__ float sden[4];
    int d = blockIdx.x;
    int tid = threadIdx.x;
    int h = tid >> 7, c = tid & 127;
    int beg = g_offB[d], end = g_offB[d+1];
    int nE = end - beg;
    float adh = g_ad1[d*4+h];
    float eself = lrelu(g_as1[d*4+h] + adh);
    float lmax = eself;
    for (int k = c; k < nE; k += 128) {
        int s = g_srcB[beg+k];
        lmax = fmaxf(lmax, lrelu(g_as1[s*4+h] + adh));
    }
    red[tid] = lmax; __syncthreads();
    for (int s = 64; s > 0; s >>= 1) {
        if (c < s) red[tid] = fmaxf(red[tid], red[tid+s]);
        __syncthreads();
    }
    float emax = red[h << 7];
    float pself = expf(eself - emax);
    float acc = pself * xw[(size_t)d*512 + tid];
    float ldenom = (c == 0) ? pself : 0.f;
    for (int base = 0; base < nE; base += 128) {
        int kmax = min(128, nE - base);
        __syncthreads();
        if (tid < kmax) src_sh[tid] = g_srcB[beg + base + tid];
        __syncthreads();
        if (c < kmax) {
            int s = src_sh[c];
            p_sh[c*4 + h] = expf(lrelu(g_as1[s*4+h] + adh) - emax);
        }
        __syncthreads();
        for (int kk = 0; kk < kmax; kk++) {
            float p = p_sh[kk*4 + h];
            acc += p * xw[(size_t)src_sh[kk]*512 + tid];
            if (c == 0) ldenom += p;
        }
    }
    if (c == 0) sden[h] = ldenom;
    __syncthreads();
    float o = fmaxf(acc / (sden[h] + 1e-16f) + bias[tid], 0.f);
    __nv_bfloat16 hi = __float2bfloat16_rn(o);
    b_z1h[(size_t)d*512 + tid] = hi;
    b_z1l[(size_t)d*512 + tid] = __float2bfloat16_rn(o - __bfloat162float(hi));
}

// ---------------- GAT layer-2 aggregation ----------------
__global__ __launch_bounds__(64)
void k_gat2_gather(const float* __restrict__ bias) {
    const float* xw = g_xwg2;
    float* z = g_z2;
    __shared__ float red[64];
    __shared__ float p_sh[64];
    __shared__ int   src_sh[64];
    __shared__ float sden;
    int d = blockIdx.x;
    int tid = threadIdx.x;
    int beg = g_offB[d], end = g_offB[d+1];
    int nE = end - beg;
    float adh = g_ad2[d];
    float eself = lrelu(g_as2[d] + adh);
    float lmax = eself;
    for (int k = tid; k < nE; k += 64)
        lmax = fmaxf(lmax, lrelu(g_as2[g_srcB[beg+k]] + adh));
    red[tid] = lmax; __syncthreads();
    for (int s = 32; s > 0; s >>= 1) {
        if (tid < s) red[tid] = fmaxf(red[tid], red[tid+s]);
        __syncthreads();
    }
    float emax = red[0];
    float pself = expf(eself - emax);
    float acc = pself * xw[d*64 + tid];
    float ldenom = (tid == 0) ? pself : 0.f;
    for (int base = 0; base < nE; base += 64) {
        int kmax = min(64, nE - base);
        __syncthreads();
        if (tid < kmax) {
            int s = g_srcB[beg + base + tid];
            src_sh[tid] = s;
            p_sh[tid] = expf(lrelu(g_as2[s] + adh) - emax);
        }
        __syncthreads();
        for (int kk = 0; kk < kmax; kk++) {
            float p = p_sh[kk];
            acc += p * xw[src_sh[kk]*64 + tid];
            if (tid == 0) ldenom += p;
        }
    }
    if (tid == 0) sden = ldenom;
    __syncthreads();
    z[d*64 + tid] = acc / (sden + 1e-16f) + bias[tid];
}

// ---------------- self-loop-only nodes ----------------
__global__ void k_zrest1(const float* __restrict__ bias) {
    int i = blockIdx.x*blockDim.x + threadIdx.x;
    if (i >= (TNV-NN)*512) return;
    size_t off = (size_t)NN*512 + i;
    float o = fmaxf(g_xwg1[off] + bias[i & 511], 0.f);
    __nv_bfloat16 hi = __float2bfloat16_rn(o);
    b_z1h[off] = hi;
    b_z1l[off] = __float2bfloat16_rn(o - __bfloat162float(hi));
}
__global__ void k_zrest2(const float* __restrict__ bias) {
    int i = blockIdx.x*blockDim.x + threadIdx.x;
    if (i >= (TNV-NN)*64) return;
    int off = NN*64 + i;
    g_z2[off] = g_xwg2[off] + bias[i & 63];
}

// ---------------- link prediction ----------------
__global__ void k_link(const int* __restrict__ eli, float* __restrict__ out) {
    const float* z = g_z2;
    int w = (blockIdx.x*blockDim.x + threadIdx.x) >> 5;
    if (w >= ELN) return;
    int lane = threadIdx.x & 31;
    int u = eli[w] & (TNV-1);
    int v = eli[ELN + w] & (TNV-1);
    float s = z[u*64+lane]*z[v*64+lane] + z[u*64+lane+32]*z[v*64+lane+32];
    for (int o = 16; o; o >>= 1) s += __shfl_down_sync(0xffffffffu, s, o);
    if (!lane) out[w] = s;
}

// ---------------- launch: two-stream fork/join ----------------
extern "C" void kernel_launch(void* const* d_in, const int* in_sizes, int n_in,
                              void* d_out, int out_size) {
    const float* x    = (const float*)d_in[0];
    const int*   ei   = (const int*)d_in[1];
    const float* ea   = (const float*)d_in[2];
    const int*   eli  = (const int*)d_in[3];
    const float* c1w = (const float*)d_in[4];
    const float* c1b = (const float*)d_in[5];
    const float* c2w = (const float*)d_in[6];
    const float* c2b = (const float*)d_in[7];
    const float* g1w = (const float*)d_in[8];
    const float* g1as = (const float*)d_in[9];
    const float* g1ad = (const float*)d_in[10];
    const float* g1b = (const float*)d_in[11];
    const float* g2w = (const float*)d_in[12];
    const float* g2as = (const float*)d_in[13];
    const float* g2ad = (const float*)d_in[14];
    const float* g2b = (const float*)d_in[15];
    const float* fcw = (const float*)d_in[16];
    const float* fcb = (const float*)d_in[17];

    float* out  = (float*)d_out;
    float* link = out;
    float* hop  = out + ELN;

    static cudaStream_t s1 = nullptr, s2 = nullptr;
    static cudaEvent_t evCvt2 = nullptr, evCvt1 = nullptr, evGraph = nullptr, evJ1 = nullptr, evJ2 = nullptr;
    if (!s1) {
        cudaStreamCreateWithFlags(&s1, cudaStreamNonBlocking);
        cudaStreamCreateWithFlags(&s2, cudaStreamNonBlocking);
        cudaEventCreateWithFlags(&evCvt2,  cudaEventDisableTiming);
        cudaEventCreateWithFlags(&evCvt1,  cudaEventDisableTiming);
        cudaEventCreateWithFlags(&evGraph, cudaEventDisableTiming);
        cudaEventCreateWithFlags(&evJ1,    cudaEventDisableTiming);
        cudaEventCreateWithFlags(&evJ2,    cudaEventDisableTiming);
        cudaFuncSetAttribute(mma_pipe<128, BF_XH,BF_XL,BF_G1WH,BF_G1WL, BUF_XWG1, 1>, cudaFuncAttributeMaxDynamicSharedMemorySize, PIPE_SMEM_128);
        cudaFuncSetAttribute(mma_pipe<128, BF_XH,BF_XL,BF_C1WH,BF_C1WL, BUF_XW1, 0>,  cudaFuncAttributeMaxDynamicSharedMemorySize, PIPE_SMEM_128);
        cudaFuncSetAttribute(mma_pipe<128, BF_H1H,BF_H1L,BF_C2WH,BF_C2WL, BUF_XW2, 0>, cudaFuncAttributeMaxDynamicSharedMemorySize, PIPE_SMEM_128);
        cudaFuncSetAttribute(mma_pipe_a2b1<128, BF_H2H,BF_H2L,BF_WF, BUF_EXT>, cudaFuncAttributeMaxDynamicSharedMemorySize, PIPE_SMEM_A2B1);
        cudaFuncSetAttribute(mma_pipe<64,  BF_Z1H,BF_Z1L,BF_G2WH,BF_G2WL, BUF_XWG2, 2>, cudaFuncAttributeMaxDynamicSharedMemorySize, PIPE_SMEM_64);
    }

    // ---- main stream head: conversions for stream-2's first GEMM ----
    k_init<<<TNV/256, 256>>>();                                                   // 0
    k_cvt<BUF_EXT, BF_XH, BF_XL><<<(TNV*DIN/4 + 255)/256, 256>>>(x, TNV*DIN/4);   // 1
    k_cvt<BUF_EXT, BF_G1WH, BF_G1WL><<<(512*DIN/4 + 255)/256, 256>>>(g1w, 512*DIN/4); // 2
    cudaEventRecord(evCvt2, 0);

    // ---- stream 2 head (slot 3 for ncu visibility): GEMM + fused att1 dots ----
    cudaStreamWaitEvent(s2, evCvt2, 0);
    mma_pipe<128, BF_XH,BF_XL,BF_G1WH,BF_G1WL, BUF_XWG1, 1>
        <<<dim3(512/128, TNV/128), 256, PIPE_SMEM_128, s2>>>(nullptr, g1as, g1ad, nullptr, TNV, 512, DIN); // 3

    // ---- main stream: rest of conversions + graph build ----
    k_cvt<BUF_EXT, BF_C1WH, BF_C1WL><<<(HID*DIN/4 + 255)/256, 256>>>(c1w, HID*DIN/4);
    cudaEventRecord(evCvt1, 0);
    k_hist<<<TEV/256, 256>>>(ei, ea);
    k_scanA<<<1, 1024>>>();
    k_scanB<<<1, 1024>>>();
    k_dinv<<<TNV/256, 256>>>();
    k_fill<<<TEV/256, 256>>>(ei, ea);
    k_weff_f16<<<(NN*HID/2 + 255)/256, 256>>>(fcw);
    k_cvt<BUF_EXT, BF_C2WH, BF_C2WL><<<(HID*HID/4 + 255)/256, 256>>>(c2w, HID*HID/4);
    k_cvt<BUF_EXT, BF_G2WH, BF_G2WL><<<(64*512/4 + 255)/256, 256>>>(g2w, 64*512/4);
    cudaEventRecord(evGraph, 0);

    // ---- stream 1: GCN hop branch ----
    cudaStreamWaitEvent(s1, evCvt1, 0);
    mma_pipe<128, BF_XH,BF_XL,BF_C1WH,BF_C1WL, BUF_XW1, 0>
        <<<dim3(1, TNV/128), 256, PIPE_SMEM_128, s1>>>(nullptr, nullptr, nullptr, nullptr, TNV, 128, DIN);
    cudaStreamWaitEvent(s1, evGraph, 0);
    k_gcn_gather<BUF_XW1, BF_H1H, BF_H1L, 0><<<TNV/4, 128, 0, s1>>>(c1b);
    mma_pipe<128, BF_H1H,BF_H1L,BF_C2WH,BF_C2WL, BUF_XW2, 0>
        <<<dim3(1, TNV/128), 256, PIPE_SMEM_128, s1>>>(nullptr, nullptr, nullptr, nullptr, TNV, 128, HID);
    k_gcn_gather<BUF_XW2, BF_H2H, BF_H2L, 1><<<TNV/4, 128, 0, s1>>>(c2b);
    mma_pipe_a2b1<128, BF_H2H,BF_H2L,BF_WF, BUF_EXT>
        <<<dim3(NN/128, TNV/128), 256, PIPE_SMEM_A2B1, s1>>>(fcb, hop, TNV, NN, HID);
    cudaEventRecord(evJ1, s1);

    // ---- stream 2 tail: GAT link branch (att dots already fused) ----
    cudaStreamWaitEvent(s2, evGraph, 0);
    k_gat1_gather<<<NN, 512, 0, s2>>>(g1b);
    k_zrest1<<<((TNV-NN)*512)/256, 256, 0, s2>>>(g1b);
    mma_pipe<64, BF_Z1H,BF_Z1L,BF_G2WH,BF_G2WL, BUF_XWG2, 2>
        <<<dim3(1, TNV/128), 256, PIPE_SMEM_64, s2>>>(nullptr, g2as, g2ad, nullptr, TNV, 64, 512);
    k_gat2_gather<<<NN, 64, 0, s2>>>(g2b);
    k_zrest2<<<((TNV-NN)*64)/256, 256, 0, s2>>>(g2b);
    k_link<<<ELN/4, 128, 0, s2>>>(eli, link);
    cudaEventRecord(evJ2, s2);

    // ---- join ----
    cudaStreamWaitEvent(0, evJ1, 0);
    cudaStreamWaitEvent(0, evJ2, 0);
}